// round 7
// baseline (speedup 1.0000x reference)
#include <cuda_runtime.h>
#include <cstdint>

#define NB        64
#define FT        51200                  // 80*640 per batch slice
#define NCH       (NB * FT)              // flatten unit per channel
#define NAUX      32
#define THRESH    20.0f
#define NTHREADS  320                    // 10 warps
#define EPL       16                     // elements per lane (4x float4)
#define TILE      512                    // elements per warp-tile (32 lanes * 16)
#define TILES_PER_SLICE (FT / TILE)      // 100
#define NWARPS    (NTHREADS / 32)        // 10
#define K1_CHUNKS 10                     // 10 blocks * 10 warps = 100 tiles per slice

__device__ unsigned g_strain_bits[NCH / 32];      // 409,600 B, lives in L2
__device__ int      g_c1p[NB * K1_CHUNKS];        // per-block partial strain counts

// peak mask for 16 consecutive elements; x[0]=prev, x[1..16]=elems, x[17]=next.
// clip(x,0) in the reference is redundant since THRESH > 0.
__device__ __forceinline__ unsigned peak_mask16(const float x[18]) {
    unsigned m = 0;
#pragma unroll
    for (int i = 0; i < 16; i++) {
        float a = x[i + 1];
        if (a >= THRESH && a > x[i] && a > x[i + 2]) m |= (1u << i);
    }
    return m;
}

// Load 16 elems + neighbors for this lane. L = channel-local index of lane's first elem.
__device__ __forceinline__ unsigned lane_peak16(const float* __restrict__ ch,
                                                unsigned L, int lane) {
    float4 v0 = *reinterpret_cast<const float4*>(ch + L);
    float4 v1 = *reinterpret_cast<const float4*>(ch + L + 4);
    float4 v2 = *reinterpret_cast<const float4*>(ch + L + 8);
    float4 v3 = *reinterpret_cast<const float4*>(ch + L + 12);
    float prev = __shfl_up_sync(0xffffffffu, v3.w, 1);
    float next = __shfl_down_sync(0xffffffffu, v0.x, 1);
    if (lane == 0)  prev = (L > 0)         ? ch[L - 1]   : INFINITY;
    if (lane == 31) next = (L + EPL < NCH) ? ch[L + EPL] : INFINITY;
    float x[18] = {prev,
                   v0.x, v0.y, v0.z, v0.w, v1.x, v1.y, v1.z, v1.w,
                   v2.x, v2.y, v2.z, v2.w, v3.x, v3.y, v3.z, v3.w,
                   next};
    return peak_mask16(x);
}

// Kernel 1: strain peak bits + partial counts. grid = (K1_CHUNKS, NB), loopless.
__global__ __launch_bounds__(NTHREADS)
void strain_mask_kernel(const float* __restrict__ qs) {
    const int b    = blockIdx.y;
    const int t    = threadIdx.x;
    const int w    = t >> 5;
    const int lane = t & 31;
    const int tile = blockIdx.x * NWARPS + w;            // 0..99
    const unsigned L = (unsigned)b * FT + (unsigned)tile * TILE + (unsigned)lane * EPL;

    unsigned m = lane_peak16(qs, L, lane);
    int cnt = __popc(m);

    // 2 lanes share one 32-bit word (16 bits each)
    unsigned word = m << (L & 16);
    word |= __shfl_xor_sync(0xffffffffu, word, 1);
    if ((lane & 1) == 0) g_strain_bits[L >> 5] = word;

    // reduce count: warp then block
#pragma unroll
    for (int o = 16; o > 0; o >>= 1) cnt += __shfl_xor_sync(0xffffffffu, cnt, o);
    __shared__ int sred[NWARPS];
    if (lane == 0) sred[w] = cnt;
    __syncthreads();
    if (t == 0) {
        int s = 0;
#pragma unroll
        for (int i = 0; i < NWARPS; i++) s += sred[i];
        g_c1p[b * K1_CHUNKS + blockIdx.x] = s;
    }
}

// Kernel 2: per (batch b, aux channel a). grid = (NB, NAUX). 10 tiles per warp.
__global__ __launch_bounds__(NTHREADS)
void aux_iou_kernel(const float* __restrict__ qa, float* __restrict__ out) {
    const int b    = blockIdx.x;
    const int a    = blockIdx.y;
    const int t    = threadIdx.x;
    const int w    = t >> 5;
    const int lane = t & 31;

    const float* __restrict__ ch = qa + (size_t)a * NCH;
    const unsigned base = (unsigned)b * FT;

    int inter = 0, c2 = 0;
    for (int tile = w; tile < TILES_PER_SLICE; tile += NWARPS) {
        const unsigned L = base + (unsigned)tile * TILE + (unsigned)lane * EPL;
        unsigned m  = lane_peak16(ch, L, lane);
        unsigned sw = g_strain_bits[L >> 5];
        unsigned sh = (sw >> (L & 16)) & 0xFFFFu;
        c2    += __popc(m);
        inter += __popc(m & sh);
    }

    // block reduce (inter, c2)
#pragma unroll
    for (int o = 16; o > 0; o >>= 1) {
        inter += __shfl_xor_sync(0xffffffffu, inter, o);
        c2    += __shfl_xor_sync(0xffffffffu, c2, o);
    }
    __shared__ int sInter[NWARPS];
    __shared__ int sC2[NWARPS];
    if (lane == 0) { sInter[w] = inter; sC2[w] = c2; }
    __syncthreads();

    if (t < 32) {
        int i2 = (t < NWARPS)    ? sInter[t] : 0;
        int k2 = (t < NWARPS)    ? sC2[t]    : 0;
        int c1 = (t < K1_CHUNKS) ? g_c1p[b * K1_CHUNKS + t] : 0;
#pragma unroll
        for (int o = 16; o > 0; o >>= 1) {
            i2 += __shfl_xor_sync(0xffffffffu, i2, o);
            k2 += __shfl_xor_sync(0xffffffffu, k2, o);
            c1 += __shfl_xor_sync(0xffffffffu, c1, o);
        }
        if (t == 0) {
            const float fi  = (float)i2;
            const float fc1 = (float)c1;
            const float fc2 = (float)k2;
            const float un  = fc1 + fc2 - fi;
            float jac, ratio;
            if (fi == 0.0f && un == 0.0f) {          // zero_union -> 1.0 both
                jac = 1.0f; ratio = 1.0f;
            } else {
                jac   = fi / un;
                ratio = (fc1 > 0.0f) ? (fi / fc1) : 0.0f;   // NaN -> 0
            }
            const int idx = a * NB + b;
            out[idx]             = jac;
            out[NAUX * NB + idx] = ratio;
        }
    }
}

extern "C" void kernel_launch(void* const* d_in, const int* in_sizes, int n_in,
                              void* d_out, int out_size) {
    const float* qt_strain = (const float*)d_in[0];   // [64, 80, 640]
    const float* qt_aux    = (const float*)d_in[1];   // [32, 64, 80, 640]
    float* out = (float*)d_out;                       // [4096] = iou ++ corr

    strain_mask_kernel<<<dim3(K1_CHUNKS, NB), NTHREADS>>>(qt_strain);
    aux_iou_kernel<<<dim3(NB, NAUX), NTHREADS>>>(qt_aux, out);
}

// round 12
// speedup vs baseline: 1.0090x; 1.0090x over previous
#include <cuda_runtime.h>
#include <cstdint>

#define NB        64
#define FT        51200                  // 80*640 per batch slice
#define NCH       (NB * FT)              // flatten unit per channel
#define NAUX      32
#define THRESH    20.0f
#define EPL       16                     // elements per lane (4x float4)
#define TILE      512                    // elements per warp-tile (32 lanes * 16)
#define TILES_PER_SLICE (FT / TILE)      // 100
#define K2_THREADS 256                   // 8 warps
#define K2_WARPS   8
#define K1_THREADS 128                   // 4 warps, one tile each
#define K1_CHUNKS  25                    // 25 blocks * 4 warps = 100 tiles per slice

__device__ unsigned g_strain_bits[NCH / 32];      // 409,600 B, lives in L2
__device__ int      g_c1p[NB * K1_CHUNKS];        // per-block partial strain counts

// peak mask for 16 consecutive elements; x[0]=prev, x[1..16]=elems, x[17]=next.
// clip(x,0) in the reference is redundant since THRESH > 0.
__device__ __forceinline__ unsigned peak_mask16(const float x[18]) {
    unsigned m = 0;
#pragma unroll
    for (int i = 0; i < 16; i++) {
        float a = x[i + 1];
        if (a >= THRESH && a > x[i] && a > x[i + 2]) m |= (1u << i);
    }
    return m;
}

// Load 16 elems + neighbors for this lane. L = channel-local index of lane's first elem.
__device__ __forceinline__ unsigned lane_peak16(const float* __restrict__ ch,
                                                unsigned L, int lane) {
    float4 v0 = *reinterpret_cast<const float4*>(ch + L);
    float4 v1 = *reinterpret_cast<const float4*>(ch + L + 4);
    float4 v2 = *reinterpret_cast<const float4*>(ch + L + 8);
    float4 v3 = *reinterpret_cast<const float4*>(ch + L + 12);
    float prev = __shfl_up_sync(0xffffffffu, v3.w, 1);
    float next = __shfl_down_sync(0xffffffffu, v0.x, 1);
    if (lane == 0)  prev = (L > 0)         ? ch[L - 1]   : INFINITY;
    if (lane == 31) next = (L + EPL < NCH) ? ch[L + EPL] : INFINITY;
    float x[18] = {prev,
                   v0.x, v0.y, v0.z, v0.w, v1.x, v1.y, v1.z, v1.w,
                   v2.x, v2.y, v2.z, v2.w, v3.x, v3.y, v3.z, v3.w,
                   next};
    return peak_mask16(x);
}

// Kernel 1: strain peak bits + partial counts. grid = (K1_CHUNKS, NB), loopless,
// one warp-tile (512 elems) per warp.
__global__ __launch_bounds__(K1_THREADS)
void strain_mask_kernel(const float* __restrict__ qs) {
    const int b    = blockIdx.y;
    const int t    = threadIdx.x;
    const int w    = t >> 5;
    const int lane = t & 31;
    const int tile = blockIdx.x * 4 + w;                 // 0..99
    const unsigned L = (unsigned)b * FT + (unsigned)tile * TILE + (unsigned)lane * EPL;

    unsigned m = lane_peak16(qs, L, lane);
    int cnt = __popc(m);

    // 2 lanes share one 32-bit word (16 bits each)
    unsigned word = m << (L & 16);
    word |= __shfl_xor_sync(0xffffffffu, word, 1);
    if ((lane & 1) == 0) g_strain_bits[L >> 5] = word;

    // reduce count: warp then block
#pragma unroll
    for (int o = 16; o > 0; o >>= 1) cnt += __shfl_xor_sync(0xffffffffu, cnt, o);
    __shared__ int sred[K1_THREADS / 32];
    if (lane == 0) sred[w] = cnt;
    __syncthreads();
    if (t == 0) {
        int s = sred[0] + sred[1] + sred[2] + sred[3];
        g_c1p[b * K1_CHUNKS + blockIdx.x] = s;
    }
}

// Kernel 2: per (batch b, aux channel a). grid = (NB, NAUX). 8 warps, 100 tiles.
__global__ __launch_bounds__(K2_THREADS)
void aux_iou_kernel(const float* __restrict__ qa, float* __restrict__ out) {
    const int b    = blockIdx.x;
    const int a    = blockIdx.y;
    const int t    = threadIdx.x;
    const int w    = t >> 5;
    const int lane = t & 31;

    const float* __restrict__ ch = qa + (size_t)a * NCH;
    const unsigned base = (unsigned)b * FT;

    int inter = 0, c2 = 0;
    for (int tile = w; tile < TILES_PER_SLICE; tile += K2_WARPS) {
        const unsigned L = base + (unsigned)tile * TILE + (unsigned)lane * EPL;
        unsigned m  = lane_peak16(ch, L, lane);
        unsigned sw = g_strain_bits[L >> 5];
        unsigned sh = (sw >> (L & 16)) & 0xFFFFu;
        c2    += __popc(m);
        inter += __popc(m & sh);
    }

    // block reduce (inter, c2)
#pragma unroll
    for (int o = 16; o > 0; o >>= 1) {
        inter += __shfl_xor_sync(0xffffffffu, inter, o);
        c2    += __shfl_xor_sync(0xffffffffu, c2, o);
    }
    __shared__ int sInter[K2_WARPS];
    __shared__ int sC2[K2_WARPS];
    if (lane == 0) { sInter[w] = inter; sC2[w] = c2; }
    __syncthreads();

    if (t < 32) {
        int i2 = (t < K2_WARPS)  ? sInter[t] : 0;
        int k2 = (t < K2_WARPS)  ? sC2[t]    : 0;
        int c1 = (t < K1_CHUNKS) ? g_c1p[b * K1_CHUNKS + t] : 0;
#pragma unroll
        for (int o = 16; o > 0; o >>= 1) {
            i2 += __shfl_xor_sync(0xffffffffu, i2, o);
            k2 += __shfl_xor_sync(0xffffffffu, k2, o);
            c1 += __shfl_xor_sync(0xffffffffu, c1, o);
        }
        if (t == 0) {
            const float fi  = (float)i2;
            const float fc1 = (float)c1;
            const float fc2 = (float)k2;
            const float un  = fc1 + fc2 - fi;
            float jac, ratio;
            if (fi == 0.0f && un == 0.0f) {          // zero_union -> 1.0 both
                jac = 1.0f; ratio = 1.0f;
            } else {
                jac   = fi / un;
                ratio = (fc1 > 0.0f) ? (fi / fc1) : 0.0f;   // NaN -> 0
            }
            const int idx = a * NB + b;
            out[idx]             = jac;
            out[NAUX * NB + idx] = ratio;
        }
    }
}

extern "C" void kernel_launch(void* const* d_in, const int* in_sizes, int n_in,
                              void* d_out, int out_size) {
    const float* qt_strain = (const float*)d_in[0];   // [64, 80, 640]
    const float* qt_aux    = (const float*)d_in[1];   // [32, 64, 80, 640]
    float* out = (float*)d_out;                       // [4096] = iou ++ corr

    strain_mask_kernel<<<dim3(K1_CHUNKS, NB), K1_THREADS>>>(qt_strain);
    aux_iou_kernel<<<dim3(NB, NAUX), K2_THREADS>>>(qt_aux, out);
}

// round 14
// speedup vs baseline: 1.1204x; 1.1104x over previous
#include <cuda_runtime.h>
#include <cstdint>

#define NB        64
#define FT        51200                  // 80*640 per batch slice
#define NCH       (NB * FT)              // flatten unit per channel
#define NAUX      32
#define THRESH    20.0f
#define WPB       (FT / 32)              // 1600 strain words per batch slice

// K1: EPL-16 loopless (measured: K1+overhead = 1.25us in R12)
#define K1_EPL     16
#define K1_TILE    512
#define K1_THREADS 128                   // 4 warps, one tile each
#define K1_CHUNKS  25                    // 25 blocks * 4 warps = 100 tiles per slice

// K2: EPL-8 (best measured variant: K2=73.0us, occ 84%)
#define K2_EPL     8
#define K2_TILE    256                   // 32 lanes * 8
#define K2_THREADS 256                   // 8 warps
#define K2_WARPS   8
#define K2_TILES   (FT / K2_TILE)        // 200

__device__ unsigned g_strain_bits[NCH / 32];      // 409,600 B, lives in L2
__device__ int      g_c1p[NB * K1_CHUNKS];        // per-block partial strain counts

// ---------------- Kernel 1: strain peak bits + partial counts ----------------
// grid = (K1_CHUNKS, NB), loopless, one 512-elem warp-tile per warp.
__global__ __launch_bounds__(K1_THREADS)
void strain_mask_kernel(const float* __restrict__ qs) {
    const int b    = blockIdx.y;
    const int t    = threadIdx.x;
    const int w    = t >> 5;
    const int lane = t & 31;
    const int tile = blockIdx.x * 4 + w;                 // 0..99
    const unsigned L = (unsigned)b * FT + (unsigned)tile * K1_TILE
                     + (unsigned)lane * K1_EPL;

    // clip(x,0) in the reference is redundant since THRESH > 0.
    float4 v0 = *reinterpret_cast<const float4*>(qs + L);
    float4 v1 = *reinterpret_cast<const float4*>(qs + L + 4);
    float4 v2 = *reinterpret_cast<const float4*>(qs + L + 8);
    float4 v3 = *reinterpret_cast<const float4*>(qs + L + 12);
    float prev = __shfl_up_sync(0xffffffffu, v3.w, 1);
    float next = __shfl_down_sync(0xffffffffu, v0.x, 1);
    if (lane == 0)  prev = (L > 0)            ? qs[L - 1]      : INFINITY;
    if (lane == 31) next = (L + K1_EPL < NCH) ? qs[L + K1_EPL] : INFINITY;
    float x[18] = {prev,
                   v0.x, v0.y, v0.z, v0.w, v1.x, v1.y, v1.z, v1.w,
                   v2.x, v2.y, v2.z, v2.w, v3.x, v3.y, v3.z, v3.w,
                   next};
    unsigned m = 0;
#pragma unroll
    for (int i = 0; i < 16; i++) {
        float a = x[i + 1];
        if (a >= THRESH && a > x[i] && a > x[i + 2]) m |= (1u << i);
    }
    int cnt = __popc(m);

    // 2 lanes share one 32-bit word (16 bits each); bit p of element at flat pos p
    unsigned word = m << (L & 16);
    word |= __shfl_xor_sync(0xffffffffu, word, 1);
    if ((lane & 1) == 0) g_strain_bits[L >> 5] = word;

#pragma unroll
    for (int o = 16; o > 0; o >>= 1) cnt += __shfl_xor_sync(0xffffffffu, cnt, o);
    __shared__ int sred[K1_THREADS / 32];
    if (lane == 0) sred[w] = cnt;
    __syncthreads();
    if (t == 0)
        g_c1p[b * K1_CHUNKS + blockIdx.x] = sred[0] + sred[1] + sred[2] + sred[3];
}

// ---------------- Kernel 2: per (batch b, aux channel a) -----------------
// grid = (NB, NAUX). EPL-8, strain bits staged in smem, aux via streaming loads.
__global__ __launch_bounds__(K2_THREADS)
void aux_iou_kernel(const float* __restrict__ qa, float* __restrict__ out) {
    const int b    = blockIdx.x;
    const int a    = blockIdx.y;
    const int t    = threadIdx.x;
    const int w    = t >> 5;
    const int lane = t & 31;

    // Stage this batch's strain bitmask into shared memory (6400 B, coalesced).
    __shared__ unsigned sbits[WPB];
    {
        const unsigned* __restrict__ gb = g_strain_bits + b * WPB;
#pragma unroll
        for (int i = 0; i < WPB / K2_THREADS; i++)          // 1600/256 -> 6 full rounds
            sbits[t + i * K2_THREADS] = gb[t + i * K2_THREADS];
        int tail = (WPB / K2_THREADS) * K2_THREADS;            // 1536
        if (t < WPB - tail) sbits[tail + t] = gb[tail + t];
    }
    __syncthreads();

    const float* __restrict__ ch = qa + (size_t)a * NCH;
    const unsigned base = (unsigned)b * FT;

    int inter = 0, c2 = 0;
#pragma unroll 2
    for (int tile = w; tile < K2_TILES; tile += K2_WARPS) {
        const unsigned L = base + (unsigned)tile * K2_TILE + (unsigned)lane * K2_EPL;
        // Streaming (evict-first) loads: this 419MB stream is touched exactly once.
        float4 v0 = __ldcs(reinterpret_cast<const float4*>(ch + L));
        float4 v1 = __ldcs(reinterpret_cast<const float4*>(ch + L + 4));
        float prev = __shfl_up_sync(0xffffffffu, v1.w, 1);
        float next = __shfl_down_sync(0xffffffffu, v0.x, 1);
        if (lane == 0)  prev = (L > 0)            ? ch[L - 1]      : INFINITY;
        if (lane == 31) next = (L + K2_EPL < NCH) ? ch[L + K2_EPL] : INFINITY;
        float x[10] = {prev, v0.x, v0.y, v0.z, v0.w, v1.x, v1.y, v1.z, v1.w, next};
        unsigned m = 0;
#pragma unroll
        for (int i = 0; i < 8; i++) {
            float av = x[i + 1];
            if (av >= THRESH && av > x[i] && av > x[i + 2]) m |= (1u << i);
        }
        // strain byte from smem (broadcast across 4 lanes; conflict-free)
        unsigned sw    = sbits[tile * 8 + (lane >> 2)];
        unsigned sbyte = (sw >> (8 * (lane & 3))) & 0xFFu;
        c2    += __popc(m);
        inter += __popc(m & sbyte);
    }

    // block reduce (inter, c2)
#pragma unroll
    for (int o = 16; o > 0; o >>= 1) {
        inter += __shfl_xor_sync(0xffffffffu, inter, o);
        c2    += __shfl_xor_sync(0xffffffffu, c2, o);
    }
    __shared__ int sInter[K2_WARPS];
    __shared__ int sC2[K2_WARPS];
    if (lane == 0) { sInter[w] = inter; sC2[w] = c2; }
    __syncthreads();

    if (t < 32) {
        int i2 = (t < K2_WARPS)  ? sInter[t] : 0;
        int k2 = (t < K2_WARPS)  ? sC2[t]    : 0;
        int c1 = (t < K1_CHUNKS) ? g_c1p[b * K1_CHUNKS + t] : 0;
#pragma unroll
        for (int o = 16; o > 0; o >>= 1) {
            i2 += __shfl_xor_sync(0xffffffffu, i2, o);
            k2 += __shfl_xor_sync(0xffffffffu, k2, o);
            c1 += __shfl_xor_sync(0xffffffffu, c1, o);
        }
        if (t == 0) {
            const float fi  = (float)i2;
            const float fc1 = (float)c1;
            const float fc2 = (float)k2;
            const float un  = fc1 + fc2 - fi;
            float jac, ratio;
            if (fi == 0.0f && un == 0.0f) {          // zero_union -> 1.0 both
                jac = 1.0f; ratio = 1.0f;
            } else {
                jac   = fi / un;
                ratio = (fc1 > 0.0f) ? (fi / fc1) : 0.0f;   // NaN -> 0
            }
            const int idx = a * NB + b;
            out[idx]             = jac;
            out[NAUX * NB + idx] = ratio;
        }
    }
}

extern "C" void kernel_launch(void* const* d_in, const int* in_sizes, int n_in,
                              void* d_out, int out_size) {
    const float* qt_strain = (const float*)d_in[0];   // [64, 80, 640]
    const float* qt_aux    = (const float*)d_in[1];   // [32, 64, 80, 640]
    float* out = (float*)d_out;                       // [4096] = iou ++ corr

    strain_mask_kernel<<<dim3(K1_CHUNKS, NB), K1_THREADS>>>(qt_strain);
    aux_iou_kernel<<<dim3(NB, NAUX), K2_THREADS>>>(qt_aux, out);
}